// round 15
// baseline (speedup 1.0000x reference)
#include <cuda_runtime.h>
#include <cuda_fp16.h>
#include <cstdint>

// ---------------------------------------------------------------------------
// QuantizedLinear: Y[8192,11008] = X[8192,4096] @ dequant(W)^T + bias
// mma.sync fp16 path (tcgen05 unavailable: harness targets plain sm_103).
// R14 (128x128 CTA, warp 32x64): 2200 us, smem-port-bound by model.
// R15: CTA 128x256, warp 64x64 (2m x 4n warps), 1 CTA/SM, 120KB smem.
//      LDSM bytes/FLOP -1.5x, STS bytes/FLOP -1.67x.
// ---------------------------------------------------------------------------

#define TOK   8192
#define INF   4096
#define OUTF  11008

#define BK      32
#define STAGES  4
#define ROWB    80                   // padded smem row stride (5 x 16B chunks)
#define ASTG    (128 * ROWB)         // 10240 B per A tile (128 rows)
#define BSTG    (256 * ROWB)         // 20480 B per B tile (256 rows)
#define STGB    (ASTG + BSTG)        // 30720 B per stage
#define SMEM_BYTES (STAGES * STGB)   // 122880
#define KT_TOT  128                  // single pass over K

// prepped operands (module-load-time scratch; no runtime alloc)
__device__ __align__(128) __half g_X[(size_t)TOK  * INF];   // 67 MB
__device__ __align__(128) __half g_W[(size_t)OUTF * INF];   // 90 MB

// -------------------- prep: x -> fp16 ---------------------------------------
__global__ void convert_x_kernel(const float* __restrict__ x) {
    size_t e = ((size_t)blockIdx.x * 256 + threadIdx.x) * 4;
    float4 v = *reinterpret_cast<const float4*>(x + e);
    __half2 p0 = __halves2half2(__float2half_rn(v.x), __float2half_rn(v.y));
    __half2 p1 = __halves2half2(__float2half_rn(v.z), __float2half_rn(v.w));
    uint2 pk = make_uint2(*reinterpret_cast<uint32_t*>(&p0),
                          *reinterpret_cast<uint32_t*>(&p1));
    *reinterpret_cast<uint2*>(g_X + e) = pk;
}

// -------------------- prep: dequant W -> fp16 --------------------------------
__global__ void dequant_w_kernel(const int* __restrict__ qw,
                                 const float* __restrict__ scales,
                                 const float* __restrict__ zeros) {
    size_t wi = ((size_t)blockIdx.x * 256 + threadIdx.x) * 4;
    int o  = (int)(wi >> 12);        // output feature
    int i0 = (int)(wi & 4095);       // input channel base (multiple of 4)
    int2 qq = *reinterpret_cast<const int2*>(qw + (size_t)o * 2048 + (i0 >> 1));
    int g = i0 >> 7;                 // group of 128 (same for all 4 cols)
    float s = scales[o * 32 + g];
    float z = zeros [o * 32 + g];
    unsigned short h[4];
    h[0] = __half_as_ushort(__float2half_rn(((float)( qq.x       & 15) - z) * s));
    h[1] = __half_as_ushort(__float2half_rn(((float)((qq.x >> 4) & 15) - z) * s));
    h[2] = __half_as_ushort(__float2half_rn(((float)( qq.y       & 15) - z) * s));
    h[3] = __half_as_ushort(__float2half_rn(((float)((qq.y >> 4) & 15) - z) * s));
    *reinterpret_cast<uint2*>(g_W + (size_t)o * INF + i0) =
        make_uint2((uint32_t)h[0] | ((uint32_t)h[1] << 16),
                   (uint32_t)h[2] | ((uint32_t)h[3] << 16));
}

// -------------------- GEMM helpers ------------------------------------------
#define LDSM4(R, addr)                                                        \
    asm volatile("ldmatrix.sync.aligned.m8n8.x4.shared.b16 {%0,%1,%2,%3}, [%4];" \
        : "=r"((R)[0]), "=r"((R)[1]), "=r"((R)[2]), "=r"((R)[3]) : "r"(addr))

#define MMA16816(C, A, B0, B1)                                                \
    asm volatile("mma.sync.aligned.m16n8k16.row.col.f32.f16.f16.f32 "         \
        "{%0,%1,%2,%3}, {%4,%5,%6,%7}, {%8,%9}, {%0,%1,%2,%3};"               \
        : "+f"((C)[0]), "+f"((C)[1]), "+f"((C)[2]), "+f"((C)[3])              \
        : "r"((A)[0]), "r"((A)[1]), "r"((A)[2]), "r"((A)[3]),                 \
          "r"(B0), "r"(B1))

// stage fill: A 128x32 (512 x 16B chunks) + B 256x32 (1024 chunks), 256 thr
static __device__ __forceinline__ void issue_stage(
    int kt, int tid, uint32_t sbase,
    const __half* __restrict__ Agm,
    const __half* __restrict__ Bgm)
{
    if (kt < KT_TOT) {
        uint32_t st = sbase + (uint32_t)(kt & 3) * STGB;
        int kOff = kt * BK;
#pragma unroll
        for (int j = 0; j < 6; j++) {
            int ch = tid + j * 256;        // 0..1535
            if (ch < 512) {
                int row = ch >> 2, c = ch & 3;
                const void* src = Agm + (size_t)row * INF + kOff + c * 8;
                uint32_t    dst = st + row * ROWB + c * 16;
                asm volatile("cp.async.cg.shared.global [%0], [%1], 16;"
                             :: "r"(dst), "l"(src));
            } else {
                int bc = ch - 512;
                int row = bc >> 2, c = bc & 3;
                const void* src = Bgm + (size_t)row * INF + kOff + c * 8;
                uint32_t    dst = st + ASTG + row * ROWB + c * 16;
                asm volatile("cp.async.cg.shared.global [%0], [%1], 16;"
                             :: "r"(dst), "l"(src));
            }
        }
    }
    asm volatile("cp.async.commit_group;" ::: "memory");
}

// -------------------- GEMM kernel -------------------------------------------
// CTA 128x256, 8 warps (2m x 4n), warp tile 64x64, BK=32, 4-stage cp.async.
__global__ void __launch_bounds__(256, 1)
gemm_kernel(const float* __restrict__ bias, float* __restrict__ out) {
    extern __shared__ __align__(1024) uint8_t smem[];
    const int tid  = threadIdx.x;
    const int lane = tid & 31;
    const int wid  = tid >> 5;
    const int wm   = wid >> 2;         // 0..1
    const int wn   = wid & 3;          // 0..3

    // supertile raster: bands of 16 m-tiles, sweep all 43 n-tiles per band
    const int bid   = blockIdx.x;
    const int band  = bid / (16 * 43);
    const int rem   = bid % (16 * 43);
    const int ntile = rem >> 4;
    const int mtile = band * 16 + (rem & 15);
    const int mBase = mtile * 128;
    const int nBase = ntile * 256;

    const __half* Agm = g_X + (size_t)mBase * INF;
    const __half* Bgm = g_W + (size_t)nBase * INF;

    const uint32_t sbase = (uint32_t)__cvta_generic_to_shared(smem);

    // per-lane ldmatrix row addresses (80B rows => (5r+c)%8 covers all banks)
    const uint32_t aLane = (uint32_t)((lane & 15) * ROWB + ((lane >> 4) & 1) * 16);
    // B NON-trans: smem [n][k] row-major == mma.row.col B fragment layout
    const uint32_t bLane = (uint32_t)(((lane & 7) + ((lane >> 4) << 3)) * ROWB
                                      + ((lane >> 3) & 1) * 16);
    const uint32_t aWarp = (uint32_t)(wm * 64) * ROWB;
    const uint32_t bWarp = (uint32_t)ASTG + (uint32_t)(wn * 64) * ROWB;

    float acc[4][8][4];
#pragma unroll
    for (int mi = 0; mi < 4; mi++)
#pragma unroll
        for (int nj = 0; nj < 8; nj++)
#pragma unroll
            for (int v = 0; v < 4; v++) acc[mi][nj][v] = 0.0f;

    // prologue: 3 stages in flight
    issue_stage(0, tid, sbase, Agm, Bgm);
    issue_stage(1, tid, sbase, Agm, Bgm);
    issue_stage(2, tid, sbase, Agm, Bgm);

    for (int kt = 0; kt < KT_TOT; kt++) {
        asm volatile("cp.async.wait_group 2;" ::: "memory");
        __syncthreads();
        issue_stage(kt + 3, tid, sbase, Agm, Bgm);

        const uint32_t st = sbase + (uint32_t)(kt & 3) * STGB;
#pragma unroll
        for (int s16 = 0; s16 < 2; s16++) {
            uint32_t a[4][4];
#pragma unroll
            for (int mi = 0; mi < 4; mi++) {
                uint32_t addr = st + aWarp + (uint32_t)(mi * 16 * ROWB)
                              + aLane + (uint32_t)(s16 * 32);
                LDSM4(a[mi], addr);
            }
            uint32_t b[4][4];
#pragma unroll
            for (int nj2 = 0; nj2 < 4; nj2++) {
                uint32_t addr = st + bWarp + (uint32_t)(nj2 * 16 * ROWB)
                              + bLane + (uint32_t)(s16 * 32);
                LDSM4(b[nj2], addr);
            }
#pragma unroll
            for (int mi = 0; mi < 4; mi++)
#pragma unroll
                for (int nj = 0; nj < 8; nj++) {
                    const uint32_t* bp = &b[nj >> 1][(nj & 1) * 2];
                    MMA16816(acc[mi][nj], a[mi], bp[0], bp[1]);
                }
        }
    }

    // epilogue: fragment layout -> global fp32 + bias
    const int g = lane >> 2;
    const int t = lane & 3;
#pragma unroll
    for (int mi = 0; mi < 4; mi++) {
        const int r0 = mBase + wm * 64 + mi * 16 + g;
#pragma unroll
        for (int nj = 0; nj < 8; nj++) {
            const int col = nBase + wn * 64 + nj * 8 + t * 2;
            const float b0 = __ldg(bias + col);
            const float b1 = __ldg(bias + col + 1);
            float2 v0 = make_float2(acc[mi][nj][0] + b0, acc[mi][nj][1] + b1);
            float2 v1 = make_float2(acc[mi][nj][2] + b0, acc[mi][nj][3] + b1);
            *reinterpret_cast<float2*>(out + (size_t)r0 * OUTF + col) = v0;
            *reinterpret_cast<float2*>(out + (size_t)(r0 + 8) * OUTF + col) = v1;
        }
    }
}

// ---------------------------------------------------------------------------
extern "C" void kernel_launch(void* const* d_in, const int* in_sizes, int n_in,
                              void* d_out, int out_size) {
    (void)in_sizes; (void)n_in; (void)out_size;
    const float* x      = (const float*)d_in[0];
    const int*   qw     = (const int*)d_in[1];
    const float* scales = (const float*)d_in[2];
    const float* zeros  = (const float*)d_in[3];
    const float* bias   = (const float*)d_in[4];
    float* out = (float*)d_out;

    convert_x_kernel<<<TOK * INF / 4 / 256, 256>>>(x);                  // 32768 blocks
    dequant_w_kernel<<<OUTF * INF / 4 / 256, 256>>>(qw, scales, zeros); // 44032 blocks

    static bool attr_set = false;  // host-side only; idempotent, no device state
    if (!attr_set) {
        cudaFuncSetAttribute(gemm_kernel,
                             cudaFuncAttributeMaxDynamicSharedMemorySize, SMEM_BYTES);
        attr_set = true;
    }
    gemm_kernel<<<(TOK / 128) * (OUTF / 256), 256, SMEM_BYTES>>>(bias, out);
}

// round 16
// speedup vs baseline: 1.1590x; 1.1590x over previous
#include <cuda_runtime.h>
#include <cuda_fp16.h>
#include <cstdint>

// ---------------------------------------------------------------------------
// QuantizedLinear: Y[8192,11008] = X[8192,4096] @ dequant(W)^T + bias
// mma.sync fp16 path (tcgen05 unavailable: harness targets plain sm_103).
// R14 (128x128 CTA, warp 32x64, occ 2, 4 stages): 2200 us  <- best
// R15 (128x256, occ 1): 2560 us REGRESSION -> occupancy-2 latency hiding is
//     the binding constraint, not smem bytes.
// R16: revert to R14 config + 5-stage pipeline + merged prep kernel
//      (2 launches/call so ncu -s 5 lands on the GEMM).
// ---------------------------------------------------------------------------

#define TOK   8192
#define INF   4096
#define OUTF  11008

#define BK      32
#define STAGES  5
#define ROWB    80                  // padded smem row stride (5 x 16B chunks)
#define ASTG    (128 * ROWB)        // 10240 B per A tile
#define STGB    (2 * ASTG)          // 20480 B per stage (A + B)
#define SMEM_BYTES (STAGES * STGB)  // 102400 -> 2 CTAs/SM (204.8 KB of 228)
#define KT_TOT  128                 // single pass over K

#define XBLKS 32768                 // prep blocks for X   (8192*4096/4/256)
#define WBLKS 44032                 // prep blocks for W   (11008*4096/4/256)

// prepped operands (module-load-time scratch; no runtime alloc)
__device__ __align__(128) __half g_X[(size_t)TOK  * INF];   // 67 MB
__device__ __align__(128) __half g_W[(size_t)OUTF * INF];   // 90 MB

// -------------------- prep: x->fp16  AND  dequant W->fp16 (merged) ----------
__global__ void prep_kernel(const float* __restrict__ x,
                            const int*   __restrict__ qw,
                            const float* __restrict__ scales,
                            const float* __restrict__ zeros) {
    if (blockIdx.x < XBLKS) {
        size_t e = ((size_t)blockIdx.x * 256 + threadIdx.x) * 4;
        float4 v = *reinterpret_cast<const float4*>(x + e);
        __half2 p0 = __halves2half2(__float2half_rn(v.x), __float2half_rn(v.y));
        __half2 p1 = __halves2half2(__float2half_rn(v.z), __float2half_rn(v.w));
        uint2 pk = make_uint2(*reinterpret_cast<uint32_t*>(&p0),
                              *reinterpret_cast<uint32_t*>(&p1));
        *reinterpret_cast<uint2*>(g_X + e) = pk;
    } else {
        size_t wi = ((size_t)(blockIdx.x - XBLKS) * 256 + threadIdx.x) * 4;
        int o  = (int)(wi >> 12);        // output feature
        int i0 = (int)(wi & 4095);       // input channel base (multiple of 4)
        int2 qq = *reinterpret_cast<const int2*>(qw + (size_t)o * 2048 + (i0 >> 1));
        int g = i0 >> 7;                 // group of 128
        float s = scales[o * 32 + g];
        float z = zeros [o * 32 + g];
        unsigned short h[4];
        h[0] = __half_as_ushort(__float2half_rn(((float)( qq.x       & 15) - z) * s));
        h[1] = __half_as_ushort(__float2half_rn(((float)((qq.x >> 4) & 15) - z) * s));
        h[2] = __half_as_ushort(__float2half_rn(((float)( qq.y       & 15) - z) * s));
        h[3] = __half_as_ushort(__float2half_rn(((float)((qq.y >> 4) & 15) - z) * s));
        *reinterpret_cast<uint2*>(g_W + (size_t)o * INF + i0) =
            make_uint2((uint32_t)h[0] | ((uint32_t)h[1] << 16),
                       (uint32_t)h[2] | ((uint32_t)h[3] << 16));
    }
}

// -------------------- GEMM helpers ------------------------------------------
#define LDSM4(R, addr)                                                        \
    asm volatile("ldmatrix.sync.aligned.m8n8.x4.shared.b16 {%0,%1,%2,%3}, [%4];" \
        : "=r"((R)[0]), "=r"((R)[1]), "=r"((R)[2]), "=r"((R)[3]) : "r"(addr))

#define MMA16816(C, A, B0, B1)                                                \
    asm volatile("mma.sync.aligned.m16n8k16.row.col.f32.f16.f16.f32 "         \
        "{%0,%1,%2,%3}, {%4,%5,%6,%7}, {%8,%9}, {%0,%1,%2,%3};"               \
        : "+f"((C)[0]), "+f"((C)[1]), "+f"((C)[2]), "+f"((C)[3])              \
        : "r"((A)[0]), "r"((A)[1]), "r"((A)[2]), "r"((A)[3]),                 \
          "r"(B0), "r"(B1))

static __device__ __forceinline__ void issue_stage(
    int kt, int tid, uint32_t sbase,
    const __half* __restrict__ Agm,
    const __half* __restrict__ Bgm)
{
    if (kt < KT_TOT) {
        uint32_t st = sbase + (uint32_t)(kt % STAGES) * STGB;
        int kOff = kt * BK;
#pragma unroll
        for (int j = 0; j < 2; j++) {
            int ch  = tid + j * 256;      // 512 16B-chunks per operand tile
            int row = ch >> 2;
            int c   = ch & 3;
            const void* asrc = Agm + (size_t)row * INF + kOff + c * 8;
            uint32_t    adst = st + row * ROWB + c * 16;
            asm volatile("cp.async.cg.shared.global [%0], [%1], 16;"
                         :: "r"(adst), "l"(asrc));
            const void* bsrc = Bgm + (size_t)row * INF + kOff + c * 8;
            uint32_t    bdst = st + ASTG + row * ROWB + c * 16;
            asm volatile("cp.async.cg.shared.global [%0], [%1], 16;"
                         :: "r"(bdst), "l"(bsrc));
        }
    }
    asm volatile("cp.async.commit_group;" ::: "memory");
}

// -------------------- GEMM kernel -------------------------------------------
// CTA 128x128, 8 warps (4m x 2n), warp tile 32x64, BK=32, 5-stage cp.async.
__global__ void __launch_bounds__(256, 2)
gemm_kernel(const float* __restrict__ bias, float* __restrict__ out) {
    extern __shared__ __align__(1024) uint8_t smem[];
    const int tid  = threadIdx.x;
    const int lane = tid & 31;
    const int wid  = tid >> 5;
    const int wm   = wid >> 1;         // 0..3
    const int wn   = wid & 1;          // 0..1

    // supertile raster: bands of 16 m-tiles, sweep all 86 n-tiles per band
    const int bid   = blockIdx.x;
    const int band  = bid / (16 * 86);
    const int rem   = bid % (16 * 86);
    const int ntile = rem >> 4;
    const int mtile = band * 16 + (rem & 15);
    const int mBase = mtile * 128;
    const int nBase = ntile * 128;

    const __half* Agm = g_X + (size_t)mBase * INF;
    const __half* Bgm = g_W + (size_t)nBase * INF;

    const uint32_t sbase = (uint32_t)__cvta_generic_to_shared(smem);

    // per-lane ldmatrix row addresses (80B rows => (5r+c)%8 covers all banks)
    const uint32_t aLane = (uint32_t)((lane & 15) * ROWB + ((lane >> 4) & 1) * 16);
    // B NON-trans: smem [n][k] row-major == mma.row.col B fragment layout
    const uint32_t bLane = (uint32_t)(((lane & 7) + ((lane >> 4) << 3)) * ROWB
                                      + ((lane >> 3) & 1) * 16);
    const uint32_t aWarp = (uint32_t)(wm * 32) * ROWB;
    const uint32_t bWarp = (uint32_t)ASTG + (uint32_t)(wn * 64) * ROWB;

    float acc[2][8][4];
#pragma unroll
    for (int mi = 0; mi < 2; mi++)
#pragma unroll
        for (int nj = 0; nj < 8; nj++)
#pragma unroll
            for (int v = 0; v < 4; v++) acc[mi][nj][v] = 0.0f;

    // prologue: 4 stages in flight
    issue_stage(0, tid, sbase, Agm, Bgm);
    issue_stage(1, tid, sbase, Agm, Bgm);
    issue_stage(2, tid, sbase, Agm, Bgm);
    issue_stage(3, tid, sbase, Agm, Bgm);

    for (int kt = 0; kt < KT_TOT; kt++) {
        asm volatile("cp.async.wait_group 3;" ::: "memory");
        __syncthreads();
        issue_stage(kt + 4, tid, sbase, Agm, Bgm);

        const uint32_t st = sbase + (uint32_t)(kt % STAGES) * STGB;
#pragma unroll
        for (int s16 = 0; s16 < 2; s16++) {
            uint32_t a[2][4];
#pragma unroll
            for (int mi = 0; mi < 2; mi++) {
                uint32_t addr = st + aWarp + (uint32_t)(mi * 16 * ROWB)
                              + aLane + (uint32_t)(s16 * 32);
                LDSM4(a[mi], addr);
            }
            uint32_t b[4][4];
#pragma unroll
            for (int nj2 = 0; nj2 < 4; nj2++) {
                uint32_t addr = st + bWarp + (uint32_t)(nj2 * 16 * ROWB)
                              + bLane + (uint32_t)(s16 * 32);
                LDSM4(b[nj2], addr);
            }
#pragma unroll
            for (int mi = 0; mi < 2; mi++)
#pragma unroll
                for (int nj = 0; nj < 8; nj++) {
                    const uint32_t* bp = &b[nj >> 1][(nj & 1) * 2];
                    MMA16816(acc[mi][nj], a[mi], bp[0], bp[1]);
                }
        }
    }

    // epilogue: fragment layout -> global fp32 + bias
    const int g = lane >> 2;
    const int t = lane & 3;
#pragma unroll
    for (int mi = 0; mi < 2; mi++) {
        const int r0 = mBase + wm * 32 + mi * 16 + g;
#pragma unroll
        for (int nj = 0; nj < 8; nj++) {
            const int col = nBase + wn * 64 + nj * 8 + t * 2;
            const float b0 = __ldg(bias + col);
            const float b1 = __ldg(bias + col + 1);
            float2 v0 = make_float2(acc[mi][nj][0] + b0, acc[mi][nj][1] + b1);
            float2 v1 = make_float2(acc[mi][nj][2] + b0, acc[mi][nj][3] + b1);
            *reinterpret_cast<float2*>(out + (size_t)r0 * OUTF + col) = v0;
            *reinterpret_cast<float2*>(out + (size_t)(r0 + 8) * OUTF + col) = v1;
        }
    }
}

// ---------------------------------------------------------------------------
extern "C" void kernel_launch(void* const* d_in, const int* in_sizes, int n_in,
                              void* d_out, int out_size) {
    (void)in_sizes; (void)n_in; (void)out_size;
    const float* x      = (const float*)d_in[0];
    const int*   qw     = (const int*)d_in[1];
    const float* scales = (const float*)d_in[2];
    const float* zeros  = (const float*)d_in[3];
    const float* bias   = (const float*)d_in[4];
    float* out = (float*)d_out;

    prep_kernel<<<XBLKS + WBLKS, 256>>>(x, qw, scales, zeros);

    static bool attr_set = false;  // host-side only; idempotent, no device state
    if (!attr_set) {
        cudaFuncSetAttribute(gemm_kernel,
                             cudaFuncAttributeMaxDynamicSharedMemorySize, SMEM_BYTES);
        attr_set = true;
    }
    gemm_kernel<<<(TOK / 128) * (OUTF / 128), 256, SMEM_BYTES>>>(bias, out);
}

// round 17
// speedup vs baseline: 1.3086x; 1.1291x over previous
#include <cuda_runtime.h>
#include <cuda_fp16.h>
#include <cstdint>

// ---------------------------------------------------------------------------
// QuantizedLinear: Y[8192,11008] = X[8192,4096] @ dequant(W)^T + bias
// mma.sync fp16 path (tcgen05 unavailable: harness targets plain sm_103).
// R14/R16 (128x128 CTA, warp 32x64, occ 2): 2200 us. GEMM profile: tensor 57%,
// L1 48%, issue 20%, occ 25% -> latency/serialization bound, nothing saturated.
// R17: (1) BK 32->64, 3 stages: half the barriers, same prefetch depth/bytes.
//      (2) interleave LDSM with MMA groups (volatile asm order is frozen, so
//          the interleave must be written explicitly).
// ---------------------------------------------------------------------------

#define TOK   8192
#define INF   4096
#define OUTF  11008

#define BK      64
#define STAGES  3
#define ROWB    144                 // 64 halves = 128B data + 16B pad (9 chunks)
#define ASTG    (128 * ROWB)        // 18432 B per operand tile
#define STGB    (2 * ASTG)          // 36864 B per stage (A + B)
#define SMEM_BYTES (STAGES * STGB)  // 110592 -> 2 CTAs/SM (221 KB of 228)
#define KT_TOT  64                  // K / BK

#define XBLKS 32768                 // prep blocks for X   (8192*4096/4/256)
#define WBLKS 44032                 // prep blocks for W   (11008*4096/4/256)

// prepped operands (module-load-time scratch; no runtime alloc)
__device__ __align__(128) __half g_X[(size_t)TOK  * INF];   // 67 MB
__device__ __align__(128) __half g_W[(size_t)OUTF * INF];   // 90 MB

// -------------------- prep: x->fp16  AND  dequant W->fp16 (merged) ----------
__global__ void prep_kernel(const float* __restrict__ x,
                            const int*   __restrict__ qw,
                            const float* __restrict__ scales,
                            const float* __restrict__ zeros) {
    if (blockIdx.x < XBLKS) {
        size_t e = ((size_t)blockIdx.x * 256 + threadIdx.x) * 4;
        float4 v = *reinterpret_cast<const float4*>(x + e);
        __half2 p0 = __halves2half2(__float2half_rn(v.x), __float2half_rn(v.y));
        __half2 p1 = __halves2half2(__float2half_rn(v.z), __float2half_rn(v.w));
        uint2 pk = make_uint2(*reinterpret_cast<uint32_t*>(&p0),
                              *reinterpret_cast<uint32_t*>(&p1));
        *reinterpret_cast<uint2*>(g_X + e) = pk;
    } else {
        size_t wi = ((size_t)(blockIdx.x - XBLKS) * 256 + threadIdx.x) * 4;
        int o  = (int)(wi >> 12);        // output feature
        int i0 = (int)(wi & 4095);       // input channel base (multiple of 4)
        int2 qq = *reinterpret_cast<const int2*>(qw + (size_t)o * 2048 + (i0 >> 1));
        int g = i0 >> 7;                 // group of 128
        float s = scales[o * 32 + g];
        float z = zeros [o * 32 + g];
        unsigned short h[4];
        h[0] = __half_as_ushort(__float2half_rn(((float)( qq.x       & 15) - z) * s));
        h[1] = __half_as_ushort(__float2half_rn(((float)((qq.x >> 4) & 15) - z) * s));
        h[2] = __half_as_ushort(__float2half_rn(((float)( qq.y       & 15) - z) * s));
        h[3] = __half_as_ushort(__float2half_rn(((float)((qq.y >> 4) & 15) - z) * s));
        *reinterpret_cast<uint2*>(g_W + (size_t)o * INF + i0) =
            make_uint2((uint32_t)h[0] | ((uint32_t)h[1] << 16),
                       (uint32_t)h[2] | ((uint32_t)h[3] << 16));
    }
}

// -------------------- GEMM helpers ------------------------------------------
#define LDSM4(R, addr)                                                        \
    asm volatile("ldmatrix.sync.aligned.m8n8.x4.shared.b16 {%0,%1,%2,%3}, [%4];" \
        : "=r"((R)[0]), "=r"((R)[1]), "=r"((R)[2]), "=r"((R)[3]) : "r"(addr))

#define MMA16816(C, A, B0, B1)                                                \
    asm volatile("mma.sync.aligned.m16n8k16.row.col.f32.f16.f16.f32 "         \
        "{%0,%1,%2,%3}, {%4,%5,%6,%7}, {%8,%9}, {%0,%1,%2,%3};"               \
        : "+f"((C)[0]), "+f"((C)[1]), "+f"((C)[2]), "+f"((C)[3])              \
        : "r"((A)[0]), "r"((A)[1]), "r"((A)[2]), "r"((A)[3]),                 \
          "r"(B0), "r"(B1))

// 4 MMAs for one b quarter (nj pair 2*q, 2*q+1)
#define MMAGRP(q)                                                             \
    MMA16816(acc[0][2*(q)],   a[0], b[q][0], b[q][1]);                        \
    MMA16816(acc[0][2*(q)+1], a[0], b[q][2], b[q][3]);                        \
    MMA16816(acc[1][2*(q)],   a[1], b[q][0], b[q][1]);                        \
    MMA16816(acc[1][2*(q)+1], a[1], b[q][2], b[q][3]);

// stage fill: A 128x64 + B 128x64 = 2048 x 16B chunks, 256 threads -> 8 each
static __device__ __forceinline__ void issue_stage(
    int kt, int tid, uint32_t sbase,
    const __half* __restrict__ Agm,
    const __half* __restrict__ Bgm)
{
    if (kt < KT_TOT) {
        uint32_t st = sbase + (uint32_t)(kt % STAGES) * STGB;
        int kOff = kt * BK;
#pragma unroll
        for (int j = 0; j < 4; j++) {
            int ch  = tid + j * 256;      // 0..1023 over A, mirrored for B
            int row = ch >> 3;
            int c   = ch & 7;
            const void* asrc = Agm + (size_t)row * INF + kOff + c * 8;
            uint32_t    adst = st + row * ROWB + c * 16;
            asm volatile("cp.async.cg.shared.global [%0], [%1], 16;"
                         :: "r"(adst), "l"(asrc));
            const void* bsrc = Bgm + (size_t)row * INF + kOff + c * 8;
            uint32_t    bdst = st + ASTG + row * ROWB + c * 16;
            asm volatile("cp.async.cg.shared.global [%0], [%1], 16;"
                         :: "r"(bdst), "l"(bsrc));
        }
    }
    asm volatile("cp.async.commit_group;" ::: "memory");
}

// -------------------- GEMM kernel -------------------------------------------
// CTA 128x128, 8 warps (4m x 2n), warp tile 32x64, BK=64, 3-stage cp.async.
__global__ void __launch_bounds__(256, 2)
gemm_kernel(const float* __restrict__ bias, float* __restrict__ out) {
    extern __shared__ __align__(1024) uint8_t smem[];
    const int tid  = threadIdx.x;
    const int lane = tid & 31;
    const int wid  = tid >> 5;
    const int wm   = wid >> 1;         // 0..3
    const int wn   = wid & 1;          // 0..1

    // supertile raster: bands of 16 m-tiles, sweep all 86 n-tiles per band
    const int bid   = blockIdx.x;
    const int band  = bid / (16 * 86);
    const int rem   = bid % (16 * 86);
    const int ntile = rem >> 4;
    const int mtile = band * 16 + (rem & 15);
    const int mBase = mtile * 128;
    const int nBase = ntile * 128;

    const __half* Agm = g_X + (size_t)mBase * INF;
    const __half* Bgm = g_W + (size_t)nBase * INF;

    const uint32_t sbase = (uint32_t)__cvta_generic_to_shared(smem);

    // per-lane ldmatrix row addresses (144B rows: 36-word stride, 4r mod 32
    // distinct over 8-row phases -> conflict-free LDSM and STS)
    const uint32_t aLane = (uint32_t)((lane & 15) * ROWB + ((lane >> 4) & 1) * 16);
    // B NON-trans: smem [n][k] row-major == mma.row.col B fragment layout
    const uint32_t bLane = (uint32_t)(((lane & 7) + ((lane >> 4) << 3)) * ROWB
                                      + ((lane >> 3) & 1) * 16);
    const uint32_t aWarp = (uint32_t)(wm * 32) * ROWB;
    const uint32_t bWarp = (uint32_t)ASTG + (uint32_t)(wn * 64) * ROWB;

    float acc[2][8][4];
#pragma unroll
    for (int mi = 0; mi < 2; mi++)
#pragma unroll
        for (int nj = 0; nj < 8; nj++)
#pragma unroll
            for (int v = 0; v < 4; v++) acc[mi][nj][v] = 0.0f;

    // prologue: 2 stages in flight
    issue_stage(0, tid, sbase, Agm, Bgm);
    issue_stage(1, tid, sbase, Agm, Bgm);

    for (int kt = 0; kt < KT_TOT; kt++) {
        asm volatile("cp.async.wait_group 1;" ::: "memory");
        __syncthreads();
        issue_stage(kt + 2, tid, sbase, Agm, Bgm);

        const uint32_t st = sbase + (uint32_t)(kt % STAGES) * STGB;
#pragma unroll
        for (int s16 = 0; s16 < 4; s16++) {
            const uint32_t ko = (uint32_t)(s16 * 32);   // 16 halves = 32 B
            uint32_t a[2][4], b[4][4];
            LDSM4(a[0], st + aWarp + aLane + ko);
            LDSM4(a[1], st + aWarp + 16 * ROWB + aLane + ko);
            LDSM4(b[0], st + bWarp + bLane + ko);
            LDSM4(b[1], st + bWarp + 16 * ROWB + bLane + ko);
            MMAGRP(0);
            LDSM4(b[2], st + bWarp + 32 * ROWB + bLane + ko);
            MMAGRP(1);
            LDSM4(b[3], st + bWarp + 48 * ROWB + bLane + ko);
            MMAGRP(2);
            MMAGRP(3);
        }
    }

    // epilogue: fragment layout -> global fp32 + bias
    const int g = lane >> 2;
    const int t = lane & 3;
#pragma unroll
    for (int mi = 0; mi < 2; mi++) {
        const int r0 = mBase + wm * 32 + mi * 16 + g;
#pragma unroll
        for (int nj = 0; nj < 8; nj++) {
            const int col = nBase + wn * 64 + nj * 8 + t * 2;
            const float b0 = __ldg(bias + col);
            const float b1 = __ldg(bias + col + 1);
            float2 v0 = make_float2(acc[mi][nj][0] + b0, acc[mi][nj][1] + b1);
            float2 v1 = make_float2(acc[mi][nj][2] + b0, acc[mi][nj][3] + b1);
            *reinterpret_cast<float2*>(out + (size_t)r0 * OUTF + col) = v0;
            *reinterpret_cast<float2*>(out + (size_t)(r0 + 8) * OUTF + col) = v1;
        }
    }
}

// ---------------------------------------------------------------------------
extern "C" void kernel_launch(void* const* d_in, const int* in_sizes, int n_in,
                              void* d_out, int out_size) {
    (void)in_sizes; (void)n_in; (void)out_size;
    const float* x      = (const float*)d_in[0];
    const int*   qw     = (const int*)d_in[1];
    const float* scales = (const float*)d_in[2];
    const float* zeros  = (const float*)d_in[3];
    const float* bias   = (const float*)d_in[4];
    float* out = (float*)d_out;

    prep_kernel<<<XBLKS + WBLKS, 256>>>(x, qw, scales, zeros);

    static bool attr_set = false;  // host-side only; idempotent, no device state
    if (!attr_set) {
        cudaFuncSetAttribute(gemm_kernel,
                             cudaFuncAttributeMaxDynamicSharedMemorySize, SMEM_BYTES);
        attr_set = true;
    }
    gemm_kernel<<<(TOK / 128) * (OUTF / 128), 256, SMEM_BYTES>>>(bias, out);
}